// round 13
// baseline (speedup 1.0000x reference)
#include <cuda_runtime.h>
#include <cuda_bf16.h>
#include <stdint.h>

// ---------------- problem constants ----------------------------------------
#define NB   32
#define HH   56
#define WW   56
#define CI   256
#define CO   256
#define HP   58
#define WP   58
#define NW_ELEM (9*CI*CO)        // 589824
#define NTPI 784                 // 28x28 tiles per image
#define NT   (NB*NTPI)           // 25088 Winograd tiles
#define NKK  256                 // 16 pos x 16 k-steps

#define NSTG        3
#define ROWPAD      48
#define A_ST        (64*ROWPAD)              // 3072 (64 tile rows)
#define STAGE_B     (A_ST + 128*ROWPAD)      // 3072 + 6144 = 9216

// ---------------- device scratch --------------------------------------------
__device__ int            g_act[NB * HP * WP * 64];        // padded s8 acts, 27.5 MB
__device__ __nv_bfloat16  g_V[(size_t)16 * NT * CI];       // transformed acts, 205 MB
__device__ __nv_bfloat16  g_U[16 * CO * CI];               // transformed weights, 2 MB
__device__ float g_partial[576];
__device__ float g_E;

// ---------------- PTX helpers ------------------------------------------------
__device__ __forceinline__ uint32_t smem_u32(const void* p) {
    uint32_t a;
    asm("{ .reg .u64 t; cvta.to.shared.u64 t, %1; cvt.u32.u64 %0, t; }" : "=r"(a) : "l"(p));
    return a;
}
#define CP_ASYNC16(dst, src) \
    asm volatile("cp.async.cg.shared.global [%0], [%1], 16;" \
        :: "r"(dst), "l"(__cvta_generic_to_global(src)))
#define CP_COMMIT() asm volatile("cp.async.commit_group;" ::: "memory")
#define CP_WAIT(n)  asm volatile("cp.async.wait_group %0;" :: "n"(n) : "memory")

__device__ __forceinline__ void hmma16816(float* d, uint32_t a0, uint32_t a1,
                                          uint32_t a2, uint32_t a3,
                                          uint32_t b0, uint32_t b1) {
    asm volatile(
        "mma.sync.aligned.m16n8k16.row.col.f32.bf16.bf16.f32 "
        "{%0,%1,%2,%3}, {%4,%5,%6,%7}, {%8,%9}, {%0,%1,%2,%3};"
        : "+f"(d[0]), "+f"(d[1]), "+f"(d[2]), "+f"(d[3])
        : "r"(a0), "r"(a1), "r"(a2), "r"(a3), "r"(b0), "r"(b1));
}

// ---------------- 1a/1b. E = mean|W| -----------------------------------------
__global__ void __launch_bounds__(256) reduce_absw_1(const float* __restrict__ W) {
    __shared__ float sh[256];
    int b = blockIdx.x, t = threadIdx.x;
    const float* p = W + b * 1024;
    sh[t] = fabsf(p[t]) + fabsf(p[t + 256]) + fabsf(p[t + 512]) + fabsf(p[t + 768]);
    __syncthreads();
    for (int o = 128; o > 0; o >>= 1) { if (t < o) sh[t] += sh[t + o]; __syncthreads(); }
    if (t == 0) g_partial[b] = sh[0];
}
__global__ void __launch_bounds__(256) reduce_absw_2() {
    __shared__ float sh[256];
    int t = threadIdx.x;
    float s = g_partial[t] + g_partial[t + 256];
    if (t < 64) s += g_partial[t + 512];
    sh[t] = s;
    __syncthreads();
    for (int o = 128; o > 0; o >>= 1) { if (t < o) sh[t] += sh[t + o]; __syncthreads(); }
    if (t == 0) g_E = sh[0] / (float)NW_ELEM;
}

// ---------------- 2. quantize acts -> padded s8 packs ------------------------
__global__ void __launch_bounds__(256) quantize_x(const float* __restrict__ x) {
    int idx = blockIdx.x * 256 + threadIdx.x;
    if (idx >= NB * HP * WP * 64) return;
    int c4 = idx & 63;
    int t  = idx >> 6;
    int wp = t % WP; t /= WP;
    int hp = t % HP;
    int n  = t / HP;
    int pack = 0;
    if (hp >= 1 && hp <= HH && wp >= 1 && wp <= WW) {
        const float4 v = *reinterpret_cast<const float4*>(
            x + (((size_t)(n * HH + (hp - 1)) * WW + (wp - 1)) * CI + c4 * 4));
        int a0 = __float2int_rn(fminf(1.0f, fabsf(v.x)) * 7.0f);
        int a1 = __float2int_rn(fminf(1.0f, fabsf(v.y)) * 7.0f);
        int a2 = __float2int_rn(fminf(1.0f, fabsf(v.z)) * 7.0f);
        int a3 = __float2int_rn(fminf(1.0f, fabsf(v.w)) * 7.0f);
        pack = (a0 & 0xff) | ((a1 & 0xff) << 8) | ((a2 & 0xff) << 16) | ((a3 & 0xff) << 24);
    }
    g_act[idx] = pack;
}

// ---------------- 3. weight transform: U2 = (2G) w (2G)^T -> bf16 ------------
__global__ void __launch_bounds__(256) wg_transform(const float* __restrict__ W) {
    int idx = blockIdx.x * 256 + threadIdx.x;
    if (idx >= CO * CI) return;
    int ci = idx & 255;
    int co = idx >> 8;
    int w[3][3];
#pragma unroll
    for (int kh = 0; kh < 3; kh++)
#pragma unroll
        for (int kw = 0; kw < 3; kw++) {
            float f = W[((size_t)((kh * 3 + kw) * CI + ci)) * CO + co];
            w[kh][kw] = (f > 0.0f) - (f < 0.0f);
        }
    int t[4][3];
#pragma unroll
    for (int c = 0; c < 3; c++) {
        t[0][c] = 2 * w[0][c];
        t[1][c] = w[0][c] + w[1][c] + w[2][c];
        t[2][c] = w[0][c] - w[1][c] + w[2][c];
        t[3][c] = 2 * w[2][c];
    }
#pragma unroll
    for (int i = 0; i < 4; i++) {
        int u[4];
        u[0] = 2 * t[i][0];
        u[1] = t[i][0] + t[i][1] + t[i][2];
        u[2] = t[i][0] - t[i][1] + t[i][2];
        u[3] = 2 * t[i][2];
#pragma unroll
        for (int j = 0; j < 4; j++)
            g_U[(((i * 4 + j) * CO + co) << 8) + ci] = __float2bfloat16((float)u[j]);
    }
}

// ---------------- 4. input transform: V = B^T d B -> bf16 --------------------
__global__ void __launch_bounds__(256) in_transform() {
    int idx = blockIdx.x * 256 + threadIdx.x;
    if (idx >= NT * 64) return;
    int cw = idx & 63;
    int T  = idx >> 6;
    int n  = T / NTPI;
    int rem = T - n * NTPI;
    int ti = rem / 28;
    int tj = rem - ti * 28;

    unsigned d[16];
#pragma unroll
    for (int r = 0; r < 4; r++)
#pragma unroll
        for (int c = 0; c < 4; c++)
            d[r * 4 + c] = (unsigned)g_act[((n * HP + 2 * ti + r) * WP + (2 * tj + c)) * 64 + cw];

    unsigned t0[4], t1[4], t2[4], t3[4];
#pragma unroll
    for (int c = 0; c < 4; c++) {
        t0[c] = __vsub4(d[0 * 4 + c], d[2 * 4 + c]);
        t1[c] = __vadd4(d[1 * 4 + c], d[2 * 4 + c]);
        t2[c] = __vsub4(d[2 * 4 + c], d[1 * 4 + c]);
        t3[c] = __vsub4(d[1 * 4 + c], d[3 * 4 + c]);
    }
    unsigned V[16];
#pragma unroll
    for (int i = 0; i < 4; i++) {
        const unsigned* t = (i == 0) ? t0 : (i == 1) ? t1 : (i == 2) ? t2 : t3;
        V[i * 4 + 0] = __vsub4(t[0], t[2]);
        V[i * 4 + 1] = __vadd4(t[1], t[2]);
        V[i * 4 + 2] = __vsub4(t[2], t[1]);
        V[i * 4 + 3] = __vsub4(t[1], t[3]);
    }
#pragma unroll
    for (int p = 0; p < 16; p++) {
        const unsigned v = V[p];
        union { __nv_bfloat16 h[4]; uint2 u; } o;
        o.h[0] = __float2bfloat16((float)(((int)(v << 24)) >> 24));
        o.h[1] = __float2bfloat16((float)(((int)(v << 16)) >> 24));
        o.h[2] = __float2bfloat16((float)(((int)(v <<  8)) >> 24));
        o.h[3] = __float2bfloat16((float)(((int)v) >> 24));
        *reinterpret_cast<uint2*>(&g_V[((size_t)p * NT + T) * CI + cw * 4]) = o.u;
    }
}

// ---------------- 5. fused GEMM + inverse transform --------------------------
// grid (392, 2); block 512 = 16 warps (4M x 4N), warp tile 16x32.
// CTA: 64 tiles x 128 co, loops over all 16 positions, folds into 4 y-accums.
__global__ void __launch_bounds__(512, 1) wino_gemm_fused(const float* __restrict__ bias,
                                                          float* __restrict__ out) {
    __shared__ char  sbuf[NSTG * STAGE_B];   // 27648 B
    __shared__ float sbias[128];

    const int tid = threadIdx.x;
    const int lane = tid & 31, wid = tid >> 5;
    const int pbase = blockIdx.x * 64;
    const int nbase = blockIdx.y * 128;
    const uint32_t sb = smem_u32(sbuf);

    if (tid < 128) sbias[tid] = bias[nbase + tid];

    // producer: threads 0-127 A (row tid>>1, half tid&1); 128-383 B
    const bool isA = tid < 128;
    const bool isB = (tid >= 128) && (tid < 384);
    const int  ac = tid, bc = tid - 128;
    const size_t aT = ((size_t)(pbase + ((ac >> 1) & 63))) * 512 + (ac & 1) * 16;
    const size_t bT = ((size_t)(nbase + ((bc >> 1) & 127))) * 512 + (bc & 1) * 16;
    const uint32_t dstA = ((ac >> 1) & 63) * ROWPAD + (ac & 1) * 16;
    const uint32_t dstB = A_ST + ((bc >> 1) & 127) * ROWPAD + (bc & 1) * 16;
    const size_t posA = (size_t)NT * 512;
    const size_t posB = (size_t)CO * 512;
    const char* gV = (const char*)g_V;
    const char* gU = (const char*)g_U;

    // consumer: 4M x 4N warps
    const int mgrp = wid & 3, ngrp = wid >> 2;
    const uint32_t aoff = (uint32_t)((mgrp * 16 + (lane >> 2)) * ROWPAD + (lane & 3) * 4);
    const uint32_t boff = (uint32_t)(A_ST + (ngrp * 32 + (lane >> 2)) * ROWPAD + (lane & 3) * 4);

    float macc[16];
    float y0[16], y1[16], y2[16], y3[16];
#pragma unroll
    for (int e = 0; e < 16; e++) {
        macc[e] = 0.0f;
        y0[e] = y1[e] = y2[e] = y3[e] = 0.0f;
    }

    // prologue kk = 0,1 (pos 0, ks 0/1)
#pragma unroll
    for (int s = 0; s < NSTG - 1; s++) {
        const uint32_t slot = sb + s * STAGE_B;
        if (isA) CP_ASYNC16(slot + dstA, gV + aT + s * 32);
        if (isB) CP_ASYNC16(slot + dstB, gU + bT + s * 32);
        CP_COMMIT();
    }

    int slot = 0, loadSlot = NSTG - 1;
    for (int kk = 0; kk < NKK; kk++) {
        CP_WAIT(NSTG - 2);
        __syncthreads();

        {
            const int kn = kk + NSTG - 1;
            if (kn < NKK) {
                const int pp = kn >> 4, ks = kn & 15;
                const uint32_t sl = sb + loadSlot * STAGE_B;
                if (isA) CP_ASYNC16(sl + dstA, gV + (size_t)pp * posA + aT + ks * 32);
                if (isB) CP_ASYNC16(sl + dstB, gU + (size_t)pp * posB + bT + ks * 32);
            }
            CP_COMMIT();
        }

        const char* s = sbuf + slot * STAGE_B;
        uint32_t af0, af1, af2, af3;
        {
            const char* ab = s + aoff;
            af0 = *(const uint32_t*)(ab);
            af1 = *(const uint32_t*)(ab + 8 * ROWPAD);
            af2 = *(const uint32_t*)(ab + 16);
            af3 = *(const uint32_t*)(ab + 8 * ROWPAD + 16);
        }
#pragma unroll
        for (int na = 0; na < 4; na++) {
            const char* bb = s + boff + na * (8 * ROWPAD);
            const uint32_t bf0 = *(const uint32_t*)(bb);
            const uint32_t bf1 = *(const uint32_t*)(bb + 16);
            hmma16816(&macc[na * 4], af0, af1, af2, af3, bf0, bf1);
        }

        if ((kk & 15) == 15) {
            // fold pos into y: y_q += a(q,pos) * macc
            const int pp = kk >> 4;
            const int r = pp >> 2, c = pp & 3;
            const float a0r = (r == 3) ? 0.0f : 1.0f;
            const float a1r = (r == 0) ? 0.0f : ((r == 1) ? 1.0f : -1.0f);
            const float a0c = (c == 3) ? 0.0f : 1.0f;
            const float a1c = (c == 0) ? 0.0f : ((c == 1) ? 1.0f : -1.0f);
            const float q00 = a0r * a0c, q01 = a0r * a1c;
            const float q10 = a1r * a0c, q11 = a1r * a1c;
#pragma unroll
            for (int e = 0; e < 16; e++) {
                const float m = macc[e];
                y0[e] = fmaf(q00, m, y0[e]);
                y1[e] = fmaf(q01, m, y1[e]);
                y2[e] = fmaf(q10, m, y2[e]);
                y3[e] = fmaf(q11, m, y3[e]);
                macc[e] = 0.0f;
            }
        }

        slot++;     if (slot == NSTG) slot = 0;
        loadSlot++; if (loadSlot == NSTG) loadSlot = 0;
    }

    // epilogue: scale + bias, write 2x2 spatial blocks
    const float scale = g_E * (1.0f / 28.0f);
    const int row0 = pbase + mgrp * 16 + (lane >> 2);
    const int col0 = nbase + ngrp * 32 + (lane & 3) * 2;
#pragma unroll
    for (int rr = 0; rr < 2; rr++) {
        const int T = row0 + rr * 8;
        const int n  = T / NTPI;
        const int rem = T - n * NTPI;
        const int ti = rem / 28;
        const int tj = rem - ti * 28;
        float* p00 = out + (((size_t)(n * HH + 2 * ti) * WW + 2 * tj) * CO);
#pragma unroll
        for (int na = 0; na < 4; na++) {
            const int col = col0 + na * 8;
            const int e0 = na * 4 + rr * 2;
            const float b0 = sbias[col - nbase];
            const float b1 = sbias[col - nbase + 1];
            float2 v;
            v.x = y0[e0] * scale + b0;  v.y = y0[e0 + 1] * scale + b1;
            *reinterpret_cast<float2*>(p00 + col) = v;
            v.x = y1[e0] * scale + b0;  v.y = y1[e0 + 1] * scale + b1;
            *reinterpret_cast<float2*>(p00 + CO + col) = v;
            v.x = y2[e0] * scale + b0;  v.y = y2[e0 + 1] * scale + b1;
            *reinterpret_cast<float2*>(p00 + (size_t)WW * CO + col) = v;
            v.x = y3[e0] * scale + b0;  v.y = y3[e0 + 1] * scale + b1;
            *reinterpret_cast<float2*>(p00 + (size_t)WW * CO + CO + col) = v;
        }
    }
}

// ---------------- launch -----------------------------------------------------
extern "C" void kernel_launch(void* const* d_in, const int* in_sizes, int n_in,
                              void* d_out, int out_size) {
    const float* x = (const float*)d_in[0];
    const float* W = (const float*)d_in[1];
    const float* b = (const float*)d_in[2];
    float* out = (float*)d_out;

    int qtot = NB * HP * WP * 64;
    quantize_x<<<(qtot + 255) / 256, 256>>>(x);
    reduce_absw_1<<<576, 256>>>(W);
    reduce_absw_2<<<1, 256>>>();
    wg_transform<<<CO * CI / 256, 256>>>(W);
    in_transform<<<(NT * 64 + 255) / 256, 256>>>();
    wino_gemm_fused<<<dim3(392, 2), 512>>>(b, out);
}

// round 15
// speedup vs baseline: 1.3247x; 1.3247x over previous
#include <cuda_runtime.h>
#include <cuda_bf16.h>
#include <stdint.h>

// ---------------- problem constants ----------------------------------------
#define NB   32
#define HH   56
#define WW   56
#define CI   256
#define CO   256
#define HP   58
#define WP   58
#define NW_ELEM (9*CI*CO)        // 589824
#define NTPI 784                 // 28x28 tiles per image
#define NT   (NB*NTPI)           // 25088 Winograd tiles
#define NKK  64                  // 4 c-positions x 16 k-steps (32B each)

#define NSTG        3
#define ROWPAD      48
#define A_ST        (128*ROWPAD)             // 6144
#define STAGE_B     (2*128*ROWPAD)           // 12288

// ---------------- device scratch --------------------------------------------
__device__ int            g_act[NB * HP * WP * 64];        // padded s8 acts, 27.5 MB
__device__ __nv_bfloat16  g_V[(size_t)16 * NT * CI];       // transformed acts, 205 MB
__device__ __nv_bfloat16  g_U[16 * CO * CI];               // transformed weights, 2 MB
__device__ float          g_Z[(size_t)8 * NT * CO];        // col-folded GEMM out, 205 MB
__device__ float g_partial[576];
__device__ float g_E;

// ---------------- PTX helpers ------------------------------------------------
__device__ __forceinline__ uint32_t smem_u32(const void* p) {
    uint32_t a;
    asm("{ .reg .u64 t; cvta.to.shared.u64 t, %1; cvt.u32.u64 %0, t; }" : "=r"(a) : "l"(p));
    return a;
}
#define CP_ASYNC16(dst, src) \
    asm volatile("cp.async.cg.shared.global [%0], [%1], 16;" \
        :: "r"(dst), "l"(__cvta_generic_to_global(src)))
#define CP_COMMIT() asm volatile("cp.async.commit_group;" ::: "memory")
#define CP_WAIT(n)  asm volatile("cp.async.wait_group %0;" :: "n"(n) : "memory")

__device__ __forceinline__ void hmma16816(float* d, uint32_t a0, uint32_t a1,
                                          uint32_t a2, uint32_t a3,
                                          uint32_t b0, uint32_t b1) {
    asm volatile(
        "mma.sync.aligned.m16n8k16.row.col.f32.bf16.bf16.f32 "
        "{%0,%1,%2,%3}, {%4,%5,%6,%7}, {%8,%9}, {%0,%1,%2,%3};"
        : "+f"(d[0]), "+f"(d[1]), "+f"(d[2]), "+f"(d[3])
        : "r"(a0), "r"(a1), "r"(a2), "r"(a3), "r"(b0), "r"(b1));
}

// ---------------- 1a/1b. E = mean|W| -----------------------------------------
__global__ void __launch_bounds__(256) reduce_absw_1(const float* __restrict__ W) {
    __shared__ float sh[256];
    int b = blockIdx.x, t = threadIdx.x;
    const float* p = W + b * 1024;
    sh[t] = fabsf(p[t]) + fabsf(p[t + 256]) + fabsf(p[t + 512]) + fabsf(p[t + 768]);
    __syncthreads();
    for (int o = 128; o > 0; o >>= 1) { if (t < o) sh[t] += sh[t + o]; __syncthreads(); }
    if (t == 0) g_partial[b] = sh[0];
}
__global__ void __launch_bounds__(256) reduce_absw_2() {
    __shared__ float sh[256];
    int t = threadIdx.x;
    float s = g_partial[t] + g_partial[t + 256];
    if (t < 64) s += g_partial[t + 512];
    sh[t] = s;
    __syncthreads();
    for (int o = 128; o > 0; o >>= 1) { if (t < o) sh[t] += sh[t + o]; __syncthreads(); }
    if (t == 0) g_E = sh[0] / (float)NW_ELEM;
}

// ---------------- 2. quantize acts -> padded s8 packs ------------------------
__global__ void __launch_bounds__(256) quantize_x(const float* __restrict__ x) {
    int idx = blockIdx.x * 256 + threadIdx.x;
    if (idx >= NB * HP * WP * 64) return;
    int c4 = idx & 63;
    int t  = idx >> 6;
    int wp = t % WP; t /= WP;
    int hp = t % HP;
    int n  = t / HP;
    int pack = 0;
    if (hp >= 1 && hp <= HH && wp >= 1 && wp <= WW) {
        const float4 v = *reinterpret_cast<const float4*>(
            x + (((size_t)(n * HH + (hp - 1)) * WW + (wp - 1)) * CI + c4 * 4));
        int a0 = __float2int_rn(fminf(1.0f, fabsf(v.x)) * 7.0f);
        int a1 = __float2int_rn(fminf(1.0f, fabsf(v.y)) * 7.0f);
        int a2 = __float2int_rn(fminf(1.0f, fabsf(v.z)) * 7.0f);
        int a3 = __float2int_rn(fminf(1.0f, fabsf(v.w)) * 7.0f);
        pack = (a0 & 0xff) | ((a1 & 0xff) << 8) | ((a2 & 0xff) << 16) | ((a3 & 0xff) << 24);
    }
    g_act[idx] = pack;
}

// ---------------- 3. weight transform: U2 = (2G) w (2G)^T -> bf16 ------------
__global__ void __launch_bounds__(256) wg_transform(const float* __restrict__ W) {
    int idx = blockIdx.x * 256 + threadIdx.x;
    if (idx >= CO * CI) return;
    int ci = idx & 255;
    int co = idx >> 8;
    int w[3][3];
#pragma unroll
    for (int kh = 0; kh < 3; kh++)
#pragma unroll
        for (int kw = 0; kw < 3; kw++) {
            float f = W[((size_t)((kh * 3 + kw) * CI + ci)) * CO + co];
            w[kh][kw] = (f > 0.0f) - (f < 0.0f);
        }
    int t[4][3];
#pragma unroll
    for (int c = 0; c < 3; c++) {
        t[0][c] = 2 * w[0][c];
        t[1][c] = w[0][c] + w[1][c] + w[2][c];
        t[2][c] = w[0][c] - w[1][c] + w[2][c];
        t[3][c] = 2 * w[2][c];
    }
#pragma unroll
    for (int i = 0; i < 4; i++) {
        int u[4];
        u[0] = 2 * t[i][0];
        u[1] = t[i][0] + t[i][1] + t[i][2];
        u[2] = t[i][0] - t[i][1] + t[i][2];
        u[3] = 2 * t[i][2];
#pragma unroll
        for (int j = 0; j < 4; j++)
            g_U[(((i * 4 + j) * CO + co) << 8) + ci] = __float2bfloat16((float)u[j]);
    }
}

// ---------------- 4. input transform: V = B^T d B -> bf16 --------------------
__global__ void __launch_bounds__(256) in_transform() {
    int idx = blockIdx.x * 256 + threadIdx.x;
    if (idx >= NT * 64) return;
    int cw = idx & 63;
    int T  = idx >> 6;
    int n  = T / NTPI;
    int rem = T - n * NTPI;
    int ti = rem / 28;
    int tj = rem - ti * 28;

    unsigned d[16];
#pragma unroll
    for (int r = 0; r < 4; r++)
#pragma unroll
        for (int c = 0; c < 4; c++)
            d[r * 4 + c] = (unsigned)g_act[((n * HP + 2 * ti + r) * WP + (2 * tj + c)) * 64 + cw];

    unsigned t0[4], t1[4], t2[4], t3[4];
#pragma unroll
    for (int c = 0; c < 4; c++) {
        t0[c] = __vsub4(d[0 * 4 + c], d[2 * 4 + c]);
        t1[c] = __vadd4(d[1 * 4 + c], d[2 * 4 + c]);
        t2[c] = __vsub4(d[2 * 4 + c], d[1 * 4 + c]);
        t3[c] = __vsub4(d[1 * 4 + c], d[3 * 4 + c]);
    }
    unsigned V[16];
#pragma unroll
    for (int i = 0; i < 4; i++) {
        const unsigned* t = (i == 0) ? t0 : (i == 1) ? t1 : (i == 2) ? t2 : t3;
        V[i * 4 + 0] = __vsub4(t[0], t[2]);
        V[i * 4 + 1] = __vadd4(t[1], t[2]);
        V[i * 4 + 2] = __vsub4(t[2], t[1]);
        V[i * 4 + 3] = __vsub4(t[1], t[3]);
    }
#pragma unroll
    for (int p = 0; p < 16; p++) {
        const unsigned v = V[p];
        union { __nv_bfloat16 h[4]; uint2 u; } o;
        o.h[0] = __float2bfloat16((float)(((int)(v << 24)) >> 24));
        o.h[1] = __float2bfloat16((float)(((int)(v << 16)) >> 24));
        o.h[2] = __float2bfloat16((float)(((int)(v <<  8)) >> 24));
        o.h[3] = __float2bfloat16((float)(((int)v) >> 24));
        *reinterpret_cast<uint2*>(&g_V[((size_t)p * NT + T) * CI + cw * 4]) = o.u;
    }
}

// ---------------- 5. GEMM with column fold -----------------------------------
// grid (196, 2, 4=r); block 512 = 16 warps (4M x 4N), warp tile 32x32.
// K-loop: c = 0..3 (positions r*4+c), 16 k-steps each; fold macc -> Z0/Z1 per c.
__global__ void __launch_bounds__(512, 1) wino_gemm_z() {
    __shared__ char sbuf[NSTG * STAGE_B];   // 36864 B

    const int tid = threadIdx.x;
    const int lane = tid & 31, wid = tid >> 5;
    const int pbase = blockIdx.x * 128;
    const int nbase = blockIdx.y * 128;
    const int r = blockIdx.z;
    const uint32_t sb = smem_u32(sbuf);

    const bool isA = tid < 256;
    const int  pc = isA ? tid : (tid - 256);
    const int  prow = pc >> 1, phalf = pc & 1;
    const char* srcBase = isA
        ? (const char*)g_V + ((size_t)(pbase + prow)) * 512 + phalf * 16
        : (const char*)g_U + ((size_t)(nbase + prow)) * 512 + phalf * 16;
    const uint32_t dstOff = (isA ? 0u : (uint32_t)A_ST) + prow * ROWPAD + phalf * 16;
    const size_t stride = isA ? (size_t)NT * 512 : (size_t)CO * 512;

    const int mgrp = wid & 3, ngrp = wid >> 2;
    const uint32_t aoff = (uint32_t)((mgrp * 32 + (lane >> 2)) * ROWPAD + (lane & 3) * 4);
    const uint32_t boff = (uint32_t)(A_ST + (ngrp * 32 + (lane >> 2)) * ROWPAD + (lane & 3) * 4);

    // macc layout: [ma(2)][na(4)][4]
    float macc[32], Z0[32], Z1[32];
#pragma unroll
    for (int e = 0; e < 32; e++) { macc[e] = 0.0f; Z0[e] = 0.0f; Z1[e] = 0.0f; }

    // prologue: kk = 0,1 (c=0, ks=0/1)
#pragma unroll
    for (int s = 0; s < NSTG - 1; s++) {
        const uint32_t slot = sb + s * STAGE_B;
        CP_ASYNC16(slot + dstOff, srcBase + (size_t)(r * 4) * stride + s * 32);
        CP_COMMIT();
    }

    int slot = 0, loadSlot = NSTG - 1;
    for (int kk = 0; kk < NKK; kk++) {
        CP_WAIT(NSTG - 2);
        __syncthreads();

        {
            const int kn = kk + NSTG - 1;
            if (kn < NKK) {
                const int c = kn >> 4, ks = kn & 15;
                const uint32_t sl = sb + loadSlot * STAGE_B;
                CP_ASYNC16(sl + dstOff, srcBase + (size_t)(r * 4 + c) * stride + ks * 32);
            }
            CP_COMMIT();
        }

        const char* s = sbuf + slot * STAGE_B;
        uint32_t af[2][4];
#pragma unroll
        for (int ma = 0; ma < 2; ma++) {
            const char* ab = s + aoff + ma * (16 * ROWPAD);
            af[ma][0] = *(const uint32_t*)(ab);
            af[ma][1] = *(const uint32_t*)(ab + 8 * ROWPAD);
            af[ma][2] = *(const uint32_t*)(ab + 16);
            af[ma][3] = *(const uint32_t*)(ab + 8 * ROWPAD + 16);
        }
#pragma unroll
        for (int na = 0; na < 4; na++) {
            const char* bb = s + boff + na * (8 * ROWPAD);
            const uint32_t bf0 = *(const uint32_t*)(bb);
            const uint32_t bf1 = *(const uint32_t*)(bb + 16);
#pragma unroll
            for (int ma = 0; ma < 2; ma++)
                hmma16816(&macc[(ma * 4 + na) * 4], af[ma][0], af[ma][1],
                          af[ma][2], af[ma][3], bf0, bf1);
        }

        if ((kk & 15) == 15) {
            const int c = kk >> 4;
#pragma unroll
            for (int e = 0; e < 32; e++) {
                const float m = macc[e];
                if (c < 3) Z0[e] += m;
                if (c == 1) Z1[e] += m;
                else if (c >= 2) Z1[e] -= m;
                macc[e] = 0.0f;
            }
        }

        slot++;     if (slot == NSTG) slot = 0;
        loadSlot++; if (loadSlot == NSTG) loadSlot = 0;
    }

    const int row0 = pbase + mgrp * 32 + (lane >> 2);
    const int col0 = nbase + ngrp * 32 + (lane & 3) * 2;
#pragma unroll
    for (int q = 0; q < 2; q++) {
        float* Zb = g_Z + ((size_t)(r * 2 + q)) * NT * CO;
        const float* Zr = (q == 0) ? Z0 : Z1;
#pragma unroll
        for (int ma = 0; ma < 2; ma++) {
#pragma unroll
            for (int na = 0; na < 4; na++) {
                const float* a4 = &Zr[(ma * 4 + na) * 4];
                const int row = row0 + ma * 16;
                const int col = col0 + na * 8;
                *reinterpret_cast<float2*>(Zb + (size_t)row * CO + col) =
                    make_float2(a4[0], a4[1]);
                *reinterpret_cast<float2*>(Zb + (size_t)(row + 8) * CO + col) =
                    make_float2(a4[2], a4[3]);
            }
        }
    }
}

// ---------------- 6. output transform: row fold + scale + bias ---------------
__global__ void __launch_bounds__(256) out_transform(const float* __restrict__ bias,
                                                     float* __restrict__ out) {
    const int lane = threadIdx.x & 31, wid = threadIdx.x >> 5;
    const int T = blockIdx.x * 8 + wid;
    const int n  = T / NTPI;
    const int rem = T - n * NTPI;
    const int ti = rem / 28;
    const int tj = rem - ti * 28;
    const float scale = g_E * (1.0f / 28.0f);

#pragma unroll 1
    for (int cb = 0; cb < 8; cb++) {
        const int co = cb * 32 + lane;
        float z[4][2];
#pragma unroll
        for (int rr = 0; rr < 4; rr++)
#pragma unroll
            for (int q = 0; q < 2; q++)
                z[rr][q] = g_Z[((size_t)(rr * 2 + q) * NT + T) * CO + co];

        const float y00 = z[0][0] + z[1][0] + z[2][0];
        const float y01 = z[0][1] + z[1][1] + z[2][1];
        const float y10 = z[1][0] - z[2][0] - z[3][0];
        const float y11 = z[1][1] - z[2][1] - z[3][1];

        const float bv = bias[co];
        float* o00 = out + (((size_t)(n * HH + 2 * ti) * WW + 2 * tj) * CO + co);
        o00[0]                  = y00 * scale + bv;
        o00[CO]                 = y01 * scale + bv;
        o00[(size_t)WW*CO]      = y10 * scale + bv;
        o00[(size_t)WW*CO + CO] = y11 * scale + bv;
    }
}

// ---------------- launch -----------------------------------------------------
extern "C" void kernel_launch(void* const* d_in, const int* in_sizes, int n_in,
                              void* d_out, int out_size) {
    const float* x = (const float*)d_in[0];
    const float* W = (const float*)d_in[1];
    const float* b = (const float*)d_in[2];
    float* out = (float*)d_out;

    int qtot = NB * HP * WP * 64;
    quantize_x<<<(qtot + 255) / 256, 256>>>(x);
    reduce_absw_1<<<576, 256>>>(W);
    reduce_absw_2<<<1, 256>>>();
    wg_transform<<<CO * CI / 256, 256>>>(W);
    in_transform<<<(NT * 64 + 255) / 256, 256>>>();
    wino_gemm_z<<<dim3(196, 2, 4), 512>>>();
    out_transform<<<NT / 8, 256>>>(b, out);
}